// round 9
// baseline (speedup 1.0000x reference)
#include <cuda_runtime.h>
#include <cuda_bf16.h>
#include <cuda_fp16.h>
#include <cstdint>

// ---------------------------------------------------------------------------
// Problem constants
// ---------------------------------------------------------------------------
constexpr int B_ = 8;
constexpr int N_ = 2048;
constexpr int D_ = 512;
constexpr int M_ = B_ * N_;                    // 16384
constexpr float SCALE = 0.04419417382415922f;  // 1/sqrt(512)

// Split-bf16 path (QKV): CTA tile 128x64, 2-stage x 48KB = 96KB, 2 CTAs/SM
constexpr int STAGE_BYTES = 49152;
constexpr int OFF_AL = 16384;
constexpr int OFF_BH = 32768;
constexpr int OFF_BL = 40960;
// fp16 single path (scores/PV): CTA tile 128x128, 3-stage x 32KB = 96KB
constexpr int S1_STAGE = 32768;
constexpr int OFF_B1 = 16384;
constexpr int SMEM_BYTES = 98304;

// ---------------------------------------------------------------------------
// Scratch (static __device__: allocation-guard safe; zero-initialized at load)
// ---------------------------------------------------------------------------
__device__ __align__(256) __nv_bfloat16 g_xhi[(size_t)M_ * D_];
__device__ __align__(256) __nv_bfloat16 g_xlo[(size_t)M_ * D_];
__device__ __align__(256) __nv_bfloat16 g_whi[(size_t)3 * D_ * D_];
__device__ __align__(256) __nv_bfloat16 g_wlo[(size_t)3 * D_ * D_];
__device__ __align__(256) __half        g_qf[(size_t)M_ * D_];         // fp16 q
__device__ __align__(256) __half        g_kf[(size_t)M_ * D_];         // fp16 k
__device__ __align__(256) __half        g_vtf[(size_t)B_ * D_ * N_];   // fp16 V^T [b][d][n]
__device__ __align__(256) __half        g_pf[(size_t)B_ * N_ * N_];    // fp16 exp numerators
__device__ __align__(256) float         g_psum[(size_t)B_ * 16 * N_];  // per-ntile row sums
__device__ __align__(256) float         g_rinv[(size_t)B_ * N_];       // 1/rowsum
__device__ __align__(256) float         g_mean[(size_t)B_ * D_];       // colmean(V)

// ---------------------------------------------------------------------------
// Helpers
// ---------------------------------------------------------------------------
__device__ __forceinline__ uint32_t smem_u32(const void* p) {
    uint32_t a;
    asm("{ .reg .u64 t; cvta.to.shared.u64 t, %1; cvt.u32.u64 %0, t; }" : "=r"(a) : "l"(p));
    return a;
}
#define SW128(o) ((o) ^ (((o) >> 3) & 0x70))

#define CP16(dst, src) \
    asm volatile("cp.async.cg.shared.global [%0], [%1], 16;" :: "r"(dst), "l"(src) : "memory")
#define CP_COMMIT() asm volatile("cp.async.commit_group;" ::: "memory")
#define CP_WAIT1() asm volatile("cp.async.wait_group 1;" ::: "memory")
#define CP_WAIT0() asm volatile("cp.async.wait_group 0;" ::: "memory")

#define LDSM4(r0, r1, r2, r3, a) \
    asm volatile("ldmatrix.sync.aligned.m8n8.x4.shared.b16 {%0,%1,%2,%3}, [%4];" \
                 : "=r"(r0), "=r"(r1), "=r"(r2), "=r"(r3) : "r"(a))

#define MMA(c, a, b0, b1) \
    asm volatile("mma.sync.aligned.m16n8k16.row.col.f32.bf16.bf16.f32 " \
                 "{%0,%1,%2,%3},{%4,%5,%6,%7},{%8,%9},{%0,%1,%2,%3};" \
                 : "+f"((c)[0]), "+f"((c)[1]), "+f"((c)[2]), "+f"((c)[3]) \
                 : "r"((a)[0]), "r"((a)[1]), "r"((a)[2]), "r"((a)[3]), "r"(b0), "r"(b1))

#define MMA16(c, a, b0, b1) \
    asm volatile("mma.sync.aligned.m16n8k16.row.col.f32.f16.f16.f32 " \
                 "{%0,%1,%2,%3},{%4,%5,%6,%7},{%8,%9},{%0,%1,%2,%3};" \
                 : "+f"((c)[0]), "+f"((c)[1]), "+f"((c)[2]), "+f"((c)[3]) \
                 : "r"((a)[0]), "r"((a)[1]), "r"((a)[2]), "r"((a)[3]), "r"(b0), "r"(b1))

__device__ __forceinline__ void split2(float f, __nv_bfloat16& h, __nv_bfloat16& l) {
    h = __float2bfloat16_rn(f);
    l = __float2bfloat16_rn(f - __bfloat162float(h));
}

// event_lengths dtype sniffing (int64 vs int32-demoted)
__device__ __forceinline__ long long get_len(const void* lens, int b) {
    const long long* p64 = (const long long*)lens;
    long long probe = p64[0];
    if (probe >= 1 && probe <= (long long)N_) return p64[b];
    return (long long)((const int*)lens)[b];
}

// ===========================================================================
// Split-bf16 GEMM machinery (QKV projections) — proven R8 core
// ===========================================================================
__device__ __forceinline__ void load_stage(
    const __nv_bfloat16* __restrict__ Ah, const __nv_bfloat16* __restrict__ Al, int lda,
    const __nv_bfloat16* __restrict__ Bh, const __nv_bfloat16* __restrict__ Bl, int ldb,
    int m0, int n0, int k0, uint32_t sbase, int tid)
{
    #pragma unroll
    for (int i = 0; i < 4; i++) {
        int idx = tid + i * 256;
        int r = idx >> 3;
        int c16 = idx & 7;
        uint32_t off = SW128((uint32_t)(r * 128 + c16 * 16));
        CP16(sbase + off,          Ah + (size_t)(m0 + r) * lda + k0 + c16 * 8);
        CP16(sbase + OFF_AL + off, Al + (size_t)(m0 + r) * lda + k0 + c16 * 8);
    }
    #pragma unroll
    for (int i = 0; i < 2; i++) {
        int idx = tid + i * 256;
        int r = idx >> 3;
        int c16 = idx & 7;
        uint32_t off = SW128((uint32_t)(r * 128 + c16 * 16));
        CP16(sbase + OFF_BH + off, Bh + (size_t)(n0 + r) * ldb + k0 + c16 * 8);
        CP16(sbase + OFF_BL + off, Bl + (size_t)(n0 + r) * ldb + k0 + c16 * 8);
    }
    CP_COMMIT();
}

__device__ __forceinline__ void compute_chunk(uint32_t sb, int wm, int wn, int lane,
                                              float acc[2][4][4])
{
    const uint32_t rA  = sb + (uint32_t)(wm * 32 + (lane & 15)) * 128;
    const uint32_t rAl = rA + OFF_AL;
    const uint32_t rB  = sb + OFF_BH + (uint32_t)(wn * 32 + (lane & 15)) * 128;
    const uint32_t rBl = rB + 8192;
    const uint32_t xr = (uint32_t)(lane & 7) << 4;
    const uint32_t half = (uint32_t)(lane >> 4) << 4;

    #pragma unroll
    for (int ks = 0; ks < 4; ks++) {
        uint32_t c = ((uint32_t)(ks * 32) + half) ^ xr;
        uint32_t ah[2][4], bh[4][2], bl[4][2];
        #pragma unroll
        for (int ma = 0; ma < 2; ma++)
            LDSM4(ah[ma][0], ah[ma][1], ah[ma][2], ah[ma][3], rA + ma * 2048 + c);
        #pragma unroll
        for (int p = 0; p < 2; p++) {
            uint32_t t0, t1, t2, t3;
            LDSM4(t0, t1, t2, t3, rB + p * 2048 + c);
            bh[p * 2][0] = t0; bh[p * 2 + 1][0] = t1;
            bh[p * 2][1] = t2; bh[p * 2 + 1][1] = t3;
            LDSM4(t0, t1, t2, t3, rBl + p * 2048 + c);
            bl[p * 2][0] = t0; bl[p * 2 + 1][0] = t1;
            bl[p * 2][1] = t2; bl[p * 2 + 1][1] = t3;
        }
        #pragma unroll
        for (int ma = 0; ma < 2; ma++)
            #pragma unroll
            for (int na = 0; na < 4; na++) {
                MMA(acc[ma][na], ah[ma], bh[na][0], bh[na][1]);
                MMA(acc[ma][na], ah[ma], bl[na][0], bl[na][1]);
            }
        #pragma unroll
        for (int ma = 0; ma < 2; ma++) {
            uint32_t al[4];
            LDSM4(al[0], al[1], al[2], al[3], rAl + ma * 2048 + c);
            #pragma unroll
            for (int na = 0; na < 4; na++)
                MMA(acc[ma][na], al, bh[na][0], bh[na][1]);
        }
    }
}

__device__ __forceinline__ void gemm_mainloop(
    const __nv_bfloat16* Ah, const __nv_bfloat16* Al, int lda,
    const __nv_bfloat16* Bh, const __nv_bfloat16* Bl, int ldb,
    int m0, int n0, int nChunks, uint32_t sb, int tid, float acc[2][4][4])
{
    const int lane = tid & 31, wid = tid >> 5;
    const int wm = wid & 3, wn = wid >> 2;

    load_stage(Ah, Al, lda, Bh, Bl, ldb, m0, n0, 0, sb, tid);
    if (nChunks > 1)
        load_stage(Ah, Al, lda, Bh, Bl, ldb, m0, n0, 64, sb + STAGE_BYTES, tid);
    for (int c = 0; c < nChunks; c++) {
        if (c + 1 < nChunks) CP_WAIT1(); else CP_WAIT0();
        __syncthreads();
        compute_chunk(sb + (c & 1) * STAGE_BYTES, wm, wn, lane, acc);
        if (c + 2 < nChunks) {
            __syncthreads();
            load_stage(Ah, Al, lda, Bh, Bl, ldb, m0, n0, (c + 2) * 64,
                       sb + (c & 1) * STAGE_BYTES, tid);
        }
    }
}

// ===========================================================================
// fp16 single-product GEMM machinery (scores, PV) — 128x128 tile, 3-stage
// ===========================================================================
__device__ __forceinline__ void load_stage1(
    const __half* __restrict__ Af, int lda,
    const __half* __restrict__ Bf, int ldb,
    int m0, int n0, int k0, uint32_t sbase, int tid)
{
    #pragma unroll
    for (int i = 0; i < 4; i++) {
        int idx = tid + i * 256;
        int r = idx >> 3;
        int c16 = idx & 7;
        uint32_t off = SW128((uint32_t)(r * 128 + c16 * 16));
        CP16(sbase + off,          Af + (size_t)(m0 + r) * lda + k0 + c16 * 8);
        CP16(sbase + OFF_B1 + off, Bf + (size_t)(n0 + r) * ldb + k0 + c16 * 8);
    }
    CP_COMMIT();
}

__device__ __forceinline__ void compute_chunk1(uint32_t sb, int wm, int wn, int lane,
                                               float acc[2][8][4])
{
    const uint32_t rA = sb + (uint32_t)(wm * 32 + (lane & 15)) * 128;
    const uint32_t rB = sb + OFF_B1 + (uint32_t)(wn * 64 + (lane & 15)) * 128;
    const uint32_t xr = (uint32_t)(lane & 7) << 4;
    const uint32_t half = (uint32_t)(lane >> 4) << 4;

    #pragma unroll
    for (int ks = 0; ks < 4; ks++) {
        uint32_t c = ((uint32_t)(ks * 32) + half) ^ xr;
        uint32_t a[2][4], b[8][2];
        #pragma unroll
        for (int ma = 0; ma < 2; ma++)
            LDSM4(a[ma][0], a[ma][1], a[ma][2], a[ma][3], rA + ma * 2048 + c);
        #pragma unroll
        for (int p = 0; p < 4; p++) {
            uint32_t t0, t1, t2, t3;
            LDSM4(t0, t1, t2, t3, rB + p * 2048 + c);
            b[p * 2][0] = t0; b[p * 2 + 1][0] = t1;
            b[p * 2][1] = t2; b[p * 2 + 1][1] = t3;
        }
        #pragma unroll
        for (int ma = 0; ma < 2; ma++)
            #pragma unroll
            for (int na = 0; na < 8; na++)
                MMA16(acc[ma][na], a[ma], b[na][0], b[na][1]);
    }
}

__device__ __forceinline__ void gemm_mainloop1(
    const __half* Af, int lda, const __half* Bf, int ldb,
    int m0, int n0, int nChunks, uint32_t sb, int tid, float acc[2][8][4])
{
    const int lane = tid & 31, wid = tid >> 5;
    const int wm = wid & 3, wn = wid >> 2;

    load_stage1(Af, lda, Bf, ldb, m0, n0, 0, sb, tid);
    if (nChunks > 1)
        load_stage1(Af, lda, Bf, ldb, m0, n0, 64, sb + S1_STAGE, tid);
    for (int c = 0; c < nChunks; c++) {
        if (c + 1 < nChunks) CP_WAIT1(); else CP_WAIT0();
        __syncthreads();
        if (c + 2 < nChunks)
            load_stage1(Af, lda, Bf, ldb, m0, n0, (c + 2) * 64,
                        sb + ((c + 2) % 3) * S1_STAGE, tid);
        compute_chunk1(sb + (c % 3) * S1_STAGE, wm, wn, lane, acc);
    }
}

// ---------------------------------------------------------------------------
// Combined convert: x (8192 CTAs) + W q/k/v (768 CTAs)
// ---------------------------------------------------------------------------
__global__ __launch_bounds__(256) void convert_kernel(const float* __restrict__ x,
                                                      const float* __restrict__ Wq,
                                                      const float* __restrict__ Wk,
                                                      const float* __restrict__ Wv) {
    const int id = blockIdx.x;
    const float* src;
    __nv_bfloat16 *dh, *dl;
    size_t i;
    if (id < 8192) {
        src = x; dh = g_xhi; dl = g_xlo;
        i = (size_t)id * 256 + threadIdx.x;
    } else {
        int t = id - 8192;
        int z = t >> 8;
        src = (z == 0) ? Wq : (z == 1) ? Wk : Wv;
        dh = g_whi + (size_t)z * D_ * D_;
        dl = g_wlo + (size_t)z * D_ * D_;
        i = (size_t)(t & 255) * 256 + threadIdx.x;
    }
    float4 v = ((const float4*)src)[i];
    __nv_bfloat16 h0, l0, h1, l1, h2, l2, h3, l3;
    split2(v.x, h0, l0); split2(v.y, h1, l1);
    split2(v.z, h2, l2); split2(v.w, h3, l3);
    ((__nv_bfloat162*)dh)[i * 2]     = __nv_bfloat162(h0, h1);
    ((__nv_bfloat162*)dh)[i * 2 + 1] = __nv_bfloat162(h2, h3);
    ((__nv_bfloat162*)dl)[i * 2]     = __nv_bfloat162(l0, l1);
    ((__nv_bfloat162*)dl)[i * 2 + 1] = __nv_bfloat162(l2, l3);
}

// ---------------------------------------------------------------------------
// Q/K projection GEMM (z: 0=q, 1=k). Output fp16. Dead m-tiles skipped.
// ---------------------------------------------------------------------------
__global__ __launch_bounds__(256, 2) void qk_mma_kernel(const float* __restrict__ bq,
                                                        const float* __restrict__ bk,
                                                        const void* __restrict__ lens) {
    extern __shared__ char dyn[];
    uint32_t sb = smem_u32(dyn);
    const int tid = threadIdx.x, lane = tid & 31, wid = tid >> 5;
    const int wm = wid & 3, wn = wid >> 2;
    const int z = blockIdx.z;
    const int m0 = blockIdx.y * 128, n0 = blockIdx.x * 64;

    const long long L = get_len(lens, m0 >> 11);
    if ((m0 & 2047) >= L) return;

    float acc[2][4][4] = {};
    const __nv_bfloat16* Bh = g_whi + (size_t)z * D_ * D_;
    const __nv_bfloat16* Bl = g_wlo + (size_t)z * D_ * D_;
    gemm_mainloop(g_xhi, g_xlo, D_, Bh, Bl, D_, m0, n0, D_ / 64, sb, tid, acc);

    const float* bias = (z == 0) ? bq : bk;
    __half* o = (z == 0) ? g_qf : g_kf;
    #pragma unroll
    for (int ma = 0; ma < 2; ma++) {
        int m = m0 + wm * 32 + ma * 16 + (lane >> 2);
        #pragma unroll
        for (int na = 0; na < 4; na++) {
            int n = n0 + wn * 32 + na * 8 + (lane & 3) * 2;
            float bv0 = __ldg(bias + n), bv1 = __ldg(bias + n + 1);
            *(__half2*)(o + (size_t)m * D_ + n) =
                __floats2half2_rn(acc[ma][na][0] + bv0, acc[ma][na][1] + bv1);
            *(__half2*)(o + (size_t)(m + 8) * D_ + n) =
                __floats2half2_rn(acc[ma][na][2] + bv0, acc[ma][na][3] + bv1);
        }
    }
}

// ---------------------------------------------------------------------------
// MEGA1: V projection (ids 0..1023, split-bf16 mainloop, fp16 transposed out)
//      + scores GEMM (ids 1024..3071, fp16 single mainloop, 128x128 tiles)
// ---------------------------------------------------------------------------
__global__ __launch_bounds__(256, 2) void mega1_kernel(const float* __restrict__ bv,
                                                       const void* __restrict__ lens) {
    extern __shared__ char dyn[];
    uint32_t sb = smem_u32(dyn);
    const int tid = threadIdx.x, lane = tid & 31, wid = tid >> 5;
    const int wm = wid & 3, wn = wid >> 2;
    const int id = blockIdx.x;

    if (id < 1024) {
        // ---- V projection (tile 128m x 64d), output transposed fp16 ----
        const int m0 = (id >> 3) * 128, n0 = (id & 7) * 64;
        float acc[2][4][4] = {};
        const __nv_bfloat16* Bh = g_whi + (size_t)2 * D_ * D_;
        const __nv_bfloat16* Bl = g_wlo + (size_t)2 * D_ * D_;
        gemm_mainloop(g_xhi, g_xlo, D_, Bh, Bl, D_, m0, n0, D_ / 64, sb, tid, acc);

        __syncthreads();
        float* sf = (float*)dyn;   // [128][65] fp32 = 33.3KB
        #pragma unroll
        for (int ma = 0; ma < 2; ma++) {
            int r = wm * 32 + ma * 16 + (lane >> 2);
            #pragma unroll
            for (int na = 0; na < 4; na++) {
                int nl = wn * 32 + na * 8 + (lane & 3) * 2;
                float bv0 = __ldg(bv + n0 + nl), bv1 = __ldg(bv + n0 + nl + 1);
                sf[r * 65 + nl]           = acc[ma][na][0] + bv0;
                sf[r * 65 + nl + 1]       = acc[ma][na][1] + bv1;
                sf[(r + 8) * 65 + nl]     = acc[ma][na][2] + bv0;
                sf[(r + 8) * 65 + nl + 1] = acc[ma][na][3] + bv1;
            }
        }
        __syncthreads();
        const int b = m0 >> 11;
        const int mloc = m0 & 2047;
        int d = tid >> 2;                  // 0..63 (local head dim)
        int ms = (tid & 3) * 32;           // m segment
        __half* o = g_vtf + ((size_t)b * D_ + n0 + d) * N_ + mloc + ms;
        #pragma unroll
        for (int c = 0; c < 32; c += 2)
            *(__half2*)(o + c) = __floats2half2_rn(sf[(ms + c) * 65 + d],
                                                   sf[(ms + c + 1) * 65 + d]);
        return;
    }

    // ---- scores GEMM (tile 128q x 128k), fused exp, fp16 numerators ----
    const int s = id - 1024;
    const int b = s >> 8;                         // 256 tiles per batch
    const int m0 = ((s >> 4) & 15) * 128, n0 = (s & 15) * 128;
    const long long L = get_len(lens, b);
    if (m0 >= L || n0 >= L) return;

    float acc[2][8][4] = {};
    const size_t off = (size_t)b * N_ * D_;
    gemm_mainloop1(g_qf + off, D_, g_kf + off, D_, m0, n0, D_ / 64, sb, tid, acc);

    float rsum[2][2] = {};
    #pragma unroll
    for (int ma = 0; ma < 2; ma++) {
        int q0 = m0 + wm * 32 + ma * 16 + (lane >> 2);
        #pragma unroll
        for (int na = 0; na < 8; na++) {
            int kj = n0 + wn * 64 + na * 8 + (lane & 3) * 2;
            bool k0d = (kj >= L), k1d = (kj + 1 >= L);
            #pragma unroll
            for (int h = 0; h < 2; h++) {
                int q = q0 + h * 8;
                bool qd = (q >= L);
                float e0 = (qd || k0d) ? 0.f : __expf(acc[ma][na][h * 2]     * SCALE);
                float e1 = (qd || k1d) ? 0.f : __expf(acc[ma][na][h * 2 + 1] * SCALE);
                __half2 hp = __floats2half2_rn(e0, e1);
                *(__half2*)(g_pf + ((size_t)b * N_ + q) * N_ + kj) = hp;
                // accumulate the ROUNDED values for consistent normalization
                float2 fr = __half22float2(hp);
                rsum[ma][h] += fr.x + fr.y;
            }
        }
    }
    __syncthreads();
    float* ps = (float*)dyn;   // [128][2]
    #pragma unroll
    for (int ma = 0; ma < 2; ma++)
        #pragma unroll
        for (int h = 0; h < 2; h++) {
            float v = rsum[ma][h];
            v += __shfl_xor_sync(0xffffffffu, v, 1);
            v += __shfl_xor_sync(0xffffffffu, v, 2);
            if ((lane & 3) == 0) {
                int r = wm * 32 + ma * 16 + (lane >> 2) + h * 8;
                ps[r * 2 + wn] = v;
            }
        }
    __syncthreads();
    if (tid < 128) {
        float t = ps[tid * 2] + ps[tid * 2 + 1];
        g_psum[((size_t)b * 16 + (n0 >> 7)) * N_ + m0 + tid] = t;
    }
}

// ---------------------------------------------------------------------------
// MEGA2: rinv (ids 0..63) + colmean(V) (ids 64..575)
// ---------------------------------------------------------------------------
__global__ __launch_bounds__(256) void mega2_kernel() {
    const int id = blockIdx.x;
    if (id < 64) {
        int idx = id * 256 + threadIdx.x;   // b*N + q
        int b = idx >> 11, q = idx & 2047;
        float s = 0.f;
        #pragma unroll
        for (int t = 0; t < 16; t++)
            s += g_psum[((size_t)b * 16 + t) * N_ + q];
        g_rinv[idx] = (s > 0.f) ? 1.0f / s : 0.f;
        return;
    }
    int gw = (id - 64) * 8 + (threadIdx.x >> 5);
    int lane = threadIdx.x & 31;
    const __half2* ph = (const __half2*)(g_vtf + (size_t)gw * N_);
    float s = 0.f;
    for (int i = lane; i < N_ / 2; i += 32) {
        float2 f = __half22float2(ph[i]);
        s += f.x + f.y;
    }
    #pragma unroll
    for (int o = 16; o > 0; o >>= 1) s += __shfl_xor_sync(0xffffffffu, s, o);
    if (lane == 0) g_mean[gw] = s * (1.0f / N_);
}

// ---------------------------------------------------------------------------
// OUT+FILL: ids 0..511 = PV GEMM (fp16 single, 128q x 128d tiles, pred m<L);
// ids 512..8703 = fill dead rows with colmean(V).
// ---------------------------------------------------------------------------
__global__ __launch_bounds__(256, 2) void out_fill_kernel(float* __restrict__ Out,
                                                          const void* __restrict__ lens) {
    const int id = blockIdx.x;
    if (id >= 512) {
        // fill: 2 rows per CTA
        int t = id - 512;                  // 0..8191
        int b = t >> 10;
        const long long L = get_len(lens, b);
        int qi = ((t & 1023) << 1) + (threadIdx.x >> 7);
        if (qi < L) return;
        int c = threadIdx.x & 127;
        float4 v = ((const float4*)(g_mean + (size_t)b * D_))[c];
        ((float4*)(Out + ((size_t)b * N_ + qi) * D_))[c] = v;
        return;
    }

    const int b = id >> 6;
    const int rem = id & 63;
    const int m0 = (rem >> 2) * 128, n0 = (rem & 3) * 128;
    const long long L = get_len(lens, b);
    if (m0 >= L) return;
    const int Lpad = ((int)L + 127) & ~127;

    extern __shared__ char dyn[];
    uint32_t sb = smem_u32(dyn);
    const int tid = threadIdx.x, lane = tid & 31, wid = tid >> 5;
    const int wm = wid & 3, wn = wid >> 2;

    float acc[2][8][4] = {};
    gemm_mainloop1(g_pf + (size_t)b * N_ * N_, N_,
                   g_vtf + (size_t)b * D_ * N_, N_,
                   m0, n0, Lpad / 64, sb, tid, acc);

    #pragma unroll
    for (int ma = 0; ma < 2; ma++) {
        int m = m0 + wm * 32 + ma * 16 + (lane >> 2);
        float ri0 = g_rinv[(size_t)b * N_ + m];
        float ri1 = g_rinv[(size_t)b * N_ + m + 8];
        float* r0 = Out + ((size_t)b * N_ + m) * D_;
        float* r1 = Out + ((size_t)b * N_ + m + 8) * D_;
        #pragma unroll
        for (int na = 0; na < 8; na++) {
            int n = n0 + wn * 64 + na * 8 + (lane & 3) * 2;
            if (m < L)
                *(float2*)(r0 + n) = make_float2(acc[ma][na][0] * ri0, acc[ma][na][1] * ri0);
            if (m + 8 < L)
                *(float2*)(r1 + n) = make_float2(acc[ma][na][2] * ri1, acc[ma][na][3] * ri1);
        }
    }
}

// ---------------------------------------------------------------------------
extern "C" void kernel_launch(void* const* d_in, const int* in_sizes, int n_in,
                              void* d_out, int out_size)
{
    const float* x    = (const float*)d_in[0];
    const void*  lens = d_in[1];
    const float* Wq   = (const float*)d_in[2];
    const float* bq   = (const float*)d_in[3];
    const float* Wk   = (const float*)d_in[4];
    const float* bk   = (const float*)d_in[5];
    const float* Wv   = (const float*)d_in[6];
    const float* bv   = (const float*)d_in[7];
    float* out = (float*)d_out;

    cudaFuncSetAttribute(qk_mma_kernel,   cudaFuncAttributeMaxDynamicSharedMemorySize, SMEM_BYTES);
    cudaFuncSetAttribute(mega1_kernel,    cudaFuncAttributeMaxDynamicSharedMemorySize, SMEM_BYTES);
    cudaFuncSetAttribute(out_fill_kernel, cudaFuncAttributeMaxDynamicSharedMemorySize, SMEM_BYTES);

    convert_kernel<<<8960, 256>>>(x, Wq, Wk, Wv);
    qk_mma_kernel<<<dim3(D_ / 64, M_ / 128, 2), 256, SMEM_BYTES>>>(bq, bk, lens);
    mega1_kernel<<<1024 + 2048, 256, SMEM_BYTES>>>(bv, lens);
    mega2_kernel<<<64 + 512, 256>>>();
    out_fill_kernel<<<512 + 8192, 256, SMEM_BYTES>>>(out, lens);
}

// round 11
// speedup vs baseline: 2.1880x; 2.1880x over previous
#include <cuda_runtime.h>
#include <cuda_fp16.h>
#include <cstdint>

// ---------------------------------------------------------------------------
// Problem constants
// ---------------------------------------------------------------------------
constexpr int B_ = 8;
constexpr int N_ = 2048;
constexpr int D_ = 512;
constexpr int M_ = B_ * N_;                    // 16384
constexpr float SCALE = 0.04419417382415922f;  // 1/sqrt(512)

// Unified fp16 GEMM path: CTA tile 128x128, K-chunk 64, 3-stage x 32KB = 96KB,
// 2 CTAs/SM. Stage: A 16KB | B 16KB.
constexpr int S1_STAGE = 32768;
constexpr int OFF_B1 = 16384;
constexpr int SMEM_BYTES = 3 * S1_STAGE;       // 98304

// ---------------------------------------------------------------------------
// Scratch (static __device__: allocation-guard safe; zero-initialized at load)
// ---------------------------------------------------------------------------
__device__ __align__(256) __half g_xf[(size_t)M_ * D_];          // fp16 x
__device__ __align__(256) __half g_wf[(size_t)3 * D_ * D_];      // fp16 Wq|Wk|Wv
__device__ __align__(256) __half g_qf[(size_t)M_ * D_];          // fp16 q
__device__ __align__(256) __half g_kf[(size_t)M_ * D_];          // fp16 k
__device__ __align__(256) __half g_vtf[(size_t)B_ * D_ * N_];    // fp16 V^T [b][d][n]
__device__ __align__(256) __half g_pf[(size_t)B_ * N_ * N_];     // fp16 exp numerators
__device__ __align__(256) float  g_psum[(size_t)B_ * 16 * N_];   // per-ntile row sums
__device__ __align__(256) float  g_rinv[(size_t)B_ * N_];        // 1/rowsum
__device__ __align__(256) float  g_mean[(size_t)B_ * D_];        // colmean(V)

// ---------------------------------------------------------------------------
// Helpers
// ---------------------------------------------------------------------------
__device__ __forceinline__ uint32_t smem_u32(const void* p) {
    uint32_t a;
    asm("{ .reg .u64 t; cvta.to.shared.u64 t, %1; cvt.u32.u64 %0, t; }" : "=r"(a) : "l"(p));
    return a;
}
#define SW128(o) ((o) ^ (((o) >> 3) & 0x70))

#define CP16(dst, src) \
    asm volatile("cp.async.cg.shared.global [%0], [%1], 16;" :: "r"(dst), "l"(src) : "memory")
#define CP_COMMIT() asm volatile("cp.async.commit_group;" ::: "memory")
#define CP_WAIT1() asm volatile("cp.async.wait_group 1;" ::: "memory")
#define CP_WAIT0() asm volatile("cp.async.wait_group 0;" ::: "memory")

#define LDSM4(r0, r1, r2, r3, a) \
    asm volatile("ldmatrix.sync.aligned.m8n8.x4.shared.b16 {%0,%1,%2,%3}, [%4];" \
                 : "=r"(r0), "=r"(r1), "=r"(r2), "=r"(r3) : "r"(a))

#define MMA16(c, a, b0, b1) \
    asm volatile("mma.sync.aligned.m16n8k16.row.col.f32.f16.f16.f32 " \
                 "{%0,%1,%2,%3},{%4,%5,%6,%7},{%8,%9},{%0,%1,%2,%3};" \
                 : "+f"((c)[0]), "+f"((c)[1]), "+f"((c)[2]), "+f"((c)[3]) \
                 : "r"((a)[0]), "r"((a)[1]), "r"((a)[2]), "r"((a)[3]), "r"(b0), "r"(b1))

// event_lengths dtype sniffing (int64 vs int32-demoted)
__device__ __forceinline__ long long get_len(const void* lens, int b) {
    const long long* p64 = (const long long*)lens;
    long long probe = p64[0];
    if (probe >= 1 && probe <= (long long)N_) return p64[b];
    return (long long)((const int*)lens)[b];
}

// ===========================================================================
// fp16 single-product GEMM machinery — 128x128 tile, 3-stage, 8 warps
// ===========================================================================
__device__ __forceinline__ void load_stage1(
    const __half* __restrict__ Af, int lda,
    const __half* __restrict__ Bf, int ldb,
    int m0, int n0, int k0, uint32_t sbase, int tid)
{
    #pragma unroll
    for (int i = 0; i < 4; i++) {
        int idx = tid + i * 256;
        int r = idx >> 3;
        int c16 = idx & 7;
        uint32_t off = SW128((uint32_t)(r * 128 + c16 * 16));
        CP16(sbase + off,          Af + (size_t)(m0 + r) * lda + k0 + c16 * 8);
        CP16(sbase + OFF_B1 + off, Bf + (size_t)(n0 + r) * ldb + k0 + c16 * 8);
    }
    CP_COMMIT();
}

__device__ __forceinline__ void compute_chunk1(uint32_t sb, int wm, int wn, int lane,
                                               float acc[2][8][4])
{
    const uint32_t rA = sb + (uint32_t)(wm * 32 + (lane & 15)) * 128;
    const uint32_t rB = sb + OFF_B1 + (uint32_t)(wn * 64 + (lane & 15)) * 128;
    const uint32_t xr = (uint32_t)(lane & 7) << 4;
    const uint32_t half_ = (uint32_t)(lane >> 4) << 4;

    #pragma unroll
    for (int ks = 0; ks < 4; ks++) {
        uint32_t c = ((uint32_t)(ks * 32) + half_) ^ xr;
        uint32_t a[2][4], b[8][2];
        #pragma unroll
        for (int ma = 0; ma < 2; ma++)
            LDSM4(a[ma][0], a[ma][1], a[ma][2], a[ma][3], rA + ma * 2048 + c);
        #pragma unroll
        for (int p = 0; p < 4; p++) {
            uint32_t t0, t1, t2, t3;
            LDSM4(t0, t1, t2, t3, rB + p * 2048 + c);
            b[p * 2][0] = t0; b[p * 2 + 1][0] = t1;
            b[p * 2][1] = t2; b[p * 2 + 1][1] = t3;
        }
        #pragma unroll
        for (int ma = 0; ma < 2; ma++)
            #pragma unroll
            for (int na = 0; na < 8; na++)
                MMA16(acc[ma][na], a[ma], b[na][0], b[na][1]);
    }
}

__device__ __forceinline__ void gemm_mainloop1(
    const __half* Af, int lda, const __half* Bf, int ldb,
    int m0, int n0, int nChunks, uint32_t sb, int tid, float acc[2][8][4])
{
    const int lane = tid & 31, wid = tid >> 5;
    const int wm = wid & 3, wn = wid >> 2;

    load_stage1(Af, lda, Bf, ldb, m0, n0, 0, sb, tid);
    if (nChunks > 1)
        load_stage1(Af, lda, Bf, ldb, m0, n0, 64, sb + S1_STAGE, tid);
    for (int c = 0; c < nChunks; c++) {
        if (c + 1 < nChunks) CP_WAIT1(); else CP_WAIT0();
        __syncthreads();
        if (c + 2 < nChunks)
            load_stage1(Af, lda, Bf, ldb, m0, n0, (c + 2) * 64,
                        sb + ((c + 2) % 3) * S1_STAGE, tid);
        compute_chunk1(sb + (c % 3) * S1_STAGE, wm, wn, lane, acc);
    }
}

// ---------------------------------------------------------------------------
// Combined convert to fp16: x (8192 CTAs) + W q/k/v (768 CTAs)
// ---------------------------------------------------------------------------
__global__ __launch_bounds__(256) void convert_kernel(const float* __restrict__ x,
                                                      const float* __restrict__ Wq,
                                                      const float* __restrict__ Wk,
                                                      const float* __restrict__ Wv) {
    const int id = blockIdx.x;
    const float* src;
    __half* d;
    size_t i;
    if (id < 8192) {
        src = x; d = g_xf;
        i = (size_t)id * 256 + threadIdx.x;
    } else {
        int t = id - 8192;
        int z = t >> 8;
        src = (z == 0) ? Wq : (z == 1) ? Wk : Wv;
        d = g_wf + (size_t)z * D_ * D_;
        i = (size_t)(t & 255) * 256 + threadIdx.x;
    }
    float4 v = ((const float4*)src)[i];
    ((__half2*)d)[i * 2]     = __floats2half2_rn(v.x, v.y);
    ((__half2*)d)[i * 2 + 1] = __floats2half2_rn(v.z, v.w);
}

// ---------------------------------------------------------------------------
// QKV projection GEMM (z: 0=q, 1=k, 2=v transposed). fp16 single product.
// Dead m-tiles skipped for q,k.
// ---------------------------------------------------------------------------
__global__ __launch_bounds__(256, 2) void qkv_mma_kernel(const float* __restrict__ bq,
                                                         const float* __restrict__ bk,
                                                         const float* __restrict__ bv,
                                                         const void* __restrict__ lens) {
    extern __shared__ char dyn[];
    uint32_t sb = smem_u32(dyn);
    const int tid = threadIdx.x, lane = tid & 31, wid = tid >> 5;
    const int wm = wid & 3, wn = wid >> 2;
    const int z = blockIdx.z;
    const int m0 = blockIdx.y * 128, n0 = blockIdx.x * 128;

    if (z < 2) {
        const long long L = get_len(lens, m0 >> 11);
        if ((m0 & 2047) >= L) return;
    }

    float acc[2][8][4] = {};
    gemm_mainloop1(g_xf, D_, g_wf + (size_t)z * D_ * D_, D_,
                   m0, n0, D_ / 64, sb, tid, acc);

    const float* bias = (z == 0) ? bq : (z == 1) ? bk : bv;

    if (z < 2) {
        __half* o = (z == 0) ? g_qf : g_kf;
        #pragma unroll
        for (int ma = 0; ma < 2; ma++) {
            int m = m0 + wm * 32 + ma * 16 + (lane >> 2);
            #pragma unroll
            for (int na = 0; na < 8; na++) {
                int n = n0 + wn * 64 + na * 8 + (lane & 3) * 2;
                float bv0 = __ldg(bias + n), bv1 = __ldg(bias + n + 1);
                *(__half2*)(o + (size_t)m * D_ + n) =
                    __floats2half2_rn(acc[ma][na][0] + bv0, acc[ma][na][1] + bv1);
                *(__half2*)(o + (size_t)(m + 8) * D_ + n) =
                    __floats2half2_rn(acc[ma][na][2] + bv0, acc[ma][na][3] + bv1);
            }
        }
    } else {
        // V: stage fp32 tile in SMEM, write transposed fp16 [b][d][n]
        __syncthreads();
        float* sf = (float*)dyn;   // [128][129] fp32 = 66KB
        #pragma unroll
        for (int ma = 0; ma < 2; ma++) {
            int r = wm * 32 + ma * 16 + (lane >> 2);
            #pragma unroll
            for (int na = 0; na < 8; na++) {
                int nl = wn * 64 + na * 8 + (lane & 3) * 2;
                float bv0 = __ldg(bias + n0 + nl), bv1 = __ldg(bias + n0 + nl + 1);
                sf[r * 129 + nl]           = acc[ma][na][0] + bv0;
                sf[r * 129 + nl + 1]       = acc[ma][na][1] + bv1;
                sf[(r + 8) * 129 + nl]     = acc[ma][na][2] + bv0;
                sf[(r + 8) * 129 + nl + 1] = acc[ma][na][3] + bv1;
            }
        }
        __syncthreads();
        const int b = m0 >> 11;
        const int mloc = m0 & 2047;
        int d = tid >> 1;                  // 0..127 (local head dim)
        int ms = (tid & 1) * 64;           // m segment
        __half* o = g_vtf + ((size_t)b * D_ + n0 + d) * N_ + mloc + ms;
        #pragma unroll
        for (int c = 0; c < 64; c += 2)
            *(__half2*)(o + c) = __floats2half2_rn(sf[(ms + c) * 129 + d],
                                                   sf[(ms + c + 1) * 129 + d]);
    }
}

// ---------------------------------------------------------------------------
// Scores GEMM (128q x 128k tiles), fused max-free exp, fp16 numerators,
// per-tile row-sum partials. Live tiles only.
// ---------------------------------------------------------------------------
__global__ __launch_bounds__(256, 2) void scores_mma_kernel(const void* __restrict__ lens) {
    const int b = blockIdx.z;
    const int m0 = blockIdx.y * 128, n0 = blockIdx.x * 128;
    const long long L = get_len(lens, b);
    if (m0 >= L || n0 >= L) return;

    extern __shared__ char dyn[];
    uint32_t sb = smem_u32(dyn);
    const int tid = threadIdx.x, lane = tid & 31, wid = tid >> 5;
    const int wm = wid & 3, wn = wid >> 2;

    float acc[2][8][4] = {};
    const size_t off = (size_t)b * N_ * D_;
    gemm_mainloop1(g_qf + off, D_, g_kf + off, D_, m0, n0, D_ / 64, sb, tid, acc);

    float rsum[2][2] = {};
    #pragma unroll
    for (int ma = 0; ma < 2; ma++) {
        int q0 = m0 + wm * 32 + ma * 16 + (lane >> 2);
        #pragma unroll
        for (int na = 0; na < 8; na++) {
            int kj = n0 + wn * 64 + na * 8 + (lane & 3) * 2;
            bool k0d = (kj >= L), k1d = (kj + 1 >= L);
            #pragma unroll
            for (int h = 0; h < 2; h++) {
                int q = q0 + h * 8;
                bool qd = (q >= L);
                float e0 = (qd || k0d) ? 0.f : __expf(acc[ma][na][h * 2]     * SCALE);
                float e1 = (qd || k1d) ? 0.f : __expf(acc[ma][na][h * 2 + 1] * SCALE);
                __half2 hp = __floats2half2_rn(e0, e1);
                *(__half2*)(g_pf + ((size_t)b * N_ + q) * N_ + kj) = hp;
                float2 fr = __half22float2(hp);   // rounded, for consistent norm
                rsum[ma][h] += fr.x + fr.y;
            }
        }
    }
    __syncthreads();
    float* ps = (float*)dyn;   // [128][2]
    #pragma unroll
    for (int ma = 0; ma < 2; ma++)
        #pragma unroll
        for (int h = 0; h < 2; h++) {
            float v = rsum[ma][h];
            v += __shfl_xor_sync(0xffffffffu, v, 1);
            v += __shfl_xor_sync(0xffffffffu, v, 2);
            if ((lane & 3) == 0) {
                int r = wm * 32 + ma * 16 + (lane >> 2) + h * 8;
                ps[r * 2 + wn] = v;
            }
        }
    __syncthreads();
    if (tid < 128) {
        float t = ps[tid * 2] + ps[tid * 2 + 1];
        g_psum[((size_t)b * 16 + (n0 >> 7)) * N_ + m0 + tid] = t;
    }
}

// ---------------------------------------------------------------------------
// MEGA2: rinv (ids 0..63) + colmean(V) (ids 64..575)
// ---------------------------------------------------------------------------
__global__ __launch_bounds__(256) void mega2_kernel() {
    const int id = blockIdx.x;
    if (id < 64) {
        int idx = id * 256 + threadIdx.x;   // b*N + q
        int b = idx >> 11, q = idx & 2047;
        float s = 0.f;
        #pragma unroll
        for (int t = 0; t < 16; t++)
            s += g_psum[((size_t)b * 16 + t) * N_ + q];
        g_rinv[idx] = (s > 0.f) ? 1.0f / s : 0.f;
        return;
    }
    int gw = (id - 64) * 8 + (threadIdx.x >> 5);
    int lane = threadIdx.x & 31;
    const __half2* ph = (const __half2*)(g_vtf + (size_t)gw * N_);
    float s = 0.f;
    for (int i = lane; i < N_ / 2; i += 32) {
        float2 f = __half22float2(ph[i]);
        s += f.x + f.y;
    }
    #pragma unroll
    for (int o = 16; o > 0; o >>= 1) s += __shfl_xor_sync(0xffffffffu, s, o);
    if (lane == 0) g_mean[gw] = s * (1.0f / N_);
}

// ---------------------------------------------------------------------------
// OUT+FILL: ids 0..511 = PV GEMM (128q x 128d tiles, stores pred m<L);
// ids 512..8703 = fill dead rows with colmean(V).
// ---------------------------------------------------------------------------
__global__ __launch_bounds__(256, 2) void out_fill_kernel(float* __restrict__ Out,
                                                          const void* __restrict__ lens) {
    const int id = blockIdx.x;
    if (id >= 512) {
        int t = id - 512;                  // 0..8191
        int b = t >> 10;
        const long long L = get_len(lens, b);
        int qi = ((t & 1023) << 1) + (threadIdx.x >> 7);
        if (qi < L) return;
        int c = threadIdx.x & 127;
        float4 v = ((const float4*)(g_mean + (size_t)b * D_))[c];
        ((float4*)(Out + ((size_t)b * N_ + qi) * D_))[c] = v;
        return;
    }

    const int b = id >> 6;
    const int rem = id & 63;
    const int m0 = (rem >> 2) * 128, n0 = (rem & 3) * 128;
    const long long L = get_len(lens, b);
    if (m0 >= L) return;
    const int Lpad = ((int)L + 127) & ~127;

    extern __shared__ char dyn[];
    uint32_t sb = smem_u32(dyn);
    const int tid = threadIdx.x, lane = tid & 31, wid = tid >> 5;
    const int wm = wid & 3, wn = wid >> 2;

    float acc[2][8][4] = {};
    gemm_mainloop1(g_pf + (size_t)b * N_ * N_, N_,
                   g_vtf + (size_t)b * D_ * N_, N_,
                   m0, n0, Lpad / 64, sb, tid, acc);

    #pragma unroll
    for (int ma = 0; ma < 2; ma++) {
        int m = m0 + wm * 32 + ma * 16 + (lane >> 2);
        float ri0 = g_rinv[(size_t)b * N_ + m];
        float ri1 = g_rinv[(size_t)b * N_ + m + 8];
        float* r0 = Out + ((size_t)b * N_ + m) * D_;
        float* r1 = Out + ((size_t)b * N_ + m + 8) * D_;
        #pragma unroll
        for (int na = 0; na < 8; na++) {
            int n = n0 + wn * 64 + na * 8 + (lane & 3) * 2;
            if (m < L)
                *(float2*)(r0 + n) = make_float2(acc[ma][na][0] * ri0, acc[ma][na][1] * ri0);
            if (m + 8 < L)
                *(float2*)(r1 + n) = make_float2(acc[ma][na][2] * ri1, acc[ma][na][3] * ri1);
        }
    }
}

// ---------------------------------------------------------------------------
extern "C" void kernel_launch(void* const* d_in, const int* in_sizes, int n_in,
                              void* d_out, int out_size)
{
    const float* x    = (const float*)d_in[0];
    const void*  lens = d_in[1];
    const float* Wq   = (const float*)d_in[2];
    const float* bq   = (const float*)d_in[3];
    const float* Wk   = (const float*)d_in[4];
    const float* bk   = (const float*)d_in[5];
    const float* Wv   = (const float*)d_in[6];
    const float* bv   = (const float*)d_in[7];
    float* out = (float*)d_out;

    cudaFuncSetAttribute(qkv_mma_kernel,    cudaFuncAttributeMaxDynamicSharedMemorySize, SMEM_BYTES);
    cudaFuncSetAttribute(scores_mma_kernel, cudaFuncAttributeMaxDynamicSharedMemorySize, SMEM_BYTES);
    cudaFuncSetAttribute(out_fill_kernel,   cudaFuncAttributeMaxDynamicSharedMemorySize, SMEM_BYTES);

    convert_kernel<<<8960, 256>>>(x, Wq, Wk, Wv);
    qkv_mma_kernel<<<dim3(D_ / 128, M_ / 128, 3), 256, SMEM_BYTES>>>(bq, bk, bv, lens);
    scores_mma_kernel<<<dim3(N_ / 128, N_ / 128, B_), 256, SMEM_BYTES>>>(lens);
    mega2_kernel<<<64 + 512, 256>>>();
    out_fill_kernel<<<512 + 8192, 256, SMEM_BYTES>>>(out, lens);
}

// round 12
// speedup vs baseline: 2.2373x; 1.0225x over previous
#include <cuda_runtime.h>
#include <cuda_fp16.h>
#include <cstdint>

// ---------------------------------------------------------------------------
// Problem constants
// ---------------------------------------------------------------------------
constexpr int B_ = 8;
constexpr int N_ = 2048;
constexpr int D_ = 512;
constexpr int M_ = B_ * N_;                    // 16384
constexpr float SCALE = 0.04419417382415922f;  // 1/sqrt(512)

// Unified fp16 GEMM path: CTA tile 128x128, K-chunk 64, 3-stage x 32KB = 96KB,
// 2 CTAs/SM. Stage: A 16KB | B 16KB.
constexpr int S1_STAGE = 32768;
constexpr int OFF_B1 = 16384;
constexpr int SMEM_BYTES = 3 * S1_STAGE;       // 98304

// ---------------------------------------------------------------------------
// Scratch (static __device__: allocation-guard safe; zero-initialized at load)
// ---------------------------------------------------------------------------
__device__ __align__(256) __half g_xf[(size_t)M_ * D_];          // fp16 x
__device__ __align__(256) __half g_wf[(size_t)3 * D_ * D_];      // fp16 Wq|Wk|Wv
__device__ __align__(256) __half g_qf[(size_t)M_ * D_];          // fp16 q
__device__ __align__(256) __half g_kf[(size_t)M_ * D_];          // fp16 k
__device__ __align__(256) __half g_vtf[(size_t)B_ * D_ * N_];    // fp16 V^T [b][d][n]
__device__ __align__(256) __half g_pf[(size_t)B_ * N_ * N_];     // fp16 exp numerators
__device__ __align__(256) float  g_psum[(size_t)B_ * 16 * N_];   // per-ntile row sums
__device__ __align__(256) float  g_mean[(size_t)B_ * D_];        // colmean(V)

// ---------------------------------------------------------------------------
// Helpers
// ---------------------------------------------------------------------------
__device__ __forceinline__ uint32_t smem_u32(const void* p) {
    uint32_t a;
    asm("{ .reg .u64 t; cvta.to.shared.u64 t, %1; cvt.u32.u64 %0, t; }" : "=r"(a) : "l"(p));
    return a;
}
#define SW128(o) ((o) ^ (((o) >> 3) & 0x70))

#define CP16(dst, src) \
    asm volatile("cp.async.cg.shared.global [%0], [%1], 16;" :: "r"(dst), "l"(src) : "memory")
#define CP_COMMIT() asm volatile("cp.async.commit_group;" ::: "memory")
#define CP_WAIT1() asm volatile("cp.async.wait_group 1;" ::: "memory")
#define CP_WAIT0() asm volatile("cp.async.wait_group 0;" ::: "memory")

#define LDSM4(r0, r1, r2, r3, a) \
    asm volatile("ldmatrix.sync.aligned.m8n8.x4.shared.b16 {%0,%1,%2,%3}, [%4];" \
                 : "=r"(r0), "=r"(r1), "=r"(r2), "=r"(r3) : "r"(a))

#define MMA16(c, a, b0, b1) \
    asm volatile("mma.sync.aligned.m16n8k16.row.col.f32.f16.f16.f32 " \
                 "{%0,%1,%2,%3},{%4,%5,%6,%7},{%8,%9},{%0,%1,%2,%3};" \
                 : "+f"((c)[0]), "+f"((c)[1]), "+f"((c)[2]), "+f"((c)[3]) \
                 : "r"((a)[0]), "r"((a)[1]), "r"((a)[2]), "r"((a)[3]), "r"(b0), "r"(b1))

// event_lengths dtype sniffing (int64 vs int32-demoted)
__device__ __forceinline__ long long get_len(const void* lens, int b) {
    const long long* p64 = (const long long*)lens;
    long long probe = p64[0];
    if (probe >= 1 && probe <= (long long)N_) return p64[b];
    return (long long)((const int*)lens)[b];
}

// ===========================================================================
// fp16 single-product GEMM machinery — 128x128 tile, 3-stage, 8 warps
// ===========================================================================
__device__ __forceinline__ void load_stage1(
    const __half* __restrict__ Af, int lda,
    const __half* __restrict__ Bf, int ldb,
    int m0, int n0, int k0, uint32_t sbase, int tid)
{
    #pragma unroll
    for (int i = 0; i < 4; i++) {
        int idx = tid + i * 256;
        int r = idx >> 3;
        int c16 = idx & 7;
        uint32_t off = SW128((uint32_t)(r * 128 + c16 * 16));
        CP16(sbase + off,          Af + (size_t)(m0 + r) * lda + k0 + c16 * 8);
        CP16(sbase + OFF_B1 + off, Bf + (size_t)(n0 + r) * ldb + k0 + c16 * 8);
    }
    CP_COMMIT();
}

__device__ __forceinline__ void compute_chunk1(uint32_t sb, int wm, int wn, int lane,
                                               float acc[2][8][4])
{
    const uint32_t rA = sb + (uint32_t)(wm * 32 + (lane & 15)) * 128;
    const uint32_t rB = sb + OFF_B1 + (uint32_t)(wn * 64 + (lane & 15)) * 128;
    const uint32_t xr = (uint32_t)(lane & 7) << 4;
    const uint32_t half_ = (uint32_t)(lane >> 4) << 4;

    #pragma unroll
    for (int ks = 0; ks < 4; ks++) {
        uint32_t c = ((uint32_t)(ks * 32) + half_) ^ xr;
        uint32_t a[2][4], b[8][2];
        #pragma unroll
        for (int ma = 0; ma < 2; ma++)
            LDSM4(a[ma][0], a[ma][1], a[ma][2], a[ma][3], rA + ma * 2048 + c);
        #pragma unroll
        for (int p = 0; p < 4; p++) {
            uint32_t t0, t1, t2, t3;
            LDSM4(t0, t1, t2, t3, rB + p * 2048 + c);
            b[p * 2][0] = t0; b[p * 2 + 1][0] = t1;
            b[p * 2][1] = t2; b[p * 2 + 1][1] = t3;
        }
        #pragma unroll
        for (int ma = 0; ma < 2; ma++)
            #pragma unroll
            for (int na = 0; na < 8; na++)
                MMA16(acc[ma][na], a[ma], b[na][0], b[na][1]);
    }
}

__device__ __forceinline__ void gemm_mainloop1(
    const __half* Af, int lda, const __half* Bf, int ldb,
    int m0, int n0, int nChunks, uint32_t sb, int tid, float acc[2][8][4])
{
    const int lane = tid & 31, wid = tid >> 5;
    const int wm = wid & 3, wn = wid >> 2;

    load_stage1(Af, lda, Bf, ldb, m0, n0, 0, sb, tid);
    if (nChunks > 1)
        load_stage1(Af, lda, Bf, ldb, m0, n0, 64, sb + S1_STAGE, tid);
    for (int c = 0; c < nChunks; c++) {
        if (c + 1 < nChunks) CP_WAIT1(); else CP_WAIT0();
        __syncthreads();
        if (c + 2 < nChunks)
            load_stage1(Af, lda, Bf, ldb, m0, n0, (c + 2) * 64,
                        sb + ((c + 2) % 3) * S1_STAGE, tid);
        compute_chunk1(sb + (c % 3) * S1_STAGE, wm, wn, lane, acc);
    }
}

// ---------------------------------------------------------------------------
// Combined convert to fp16: x (8192 CTAs) + W q/k/v (768 CTAs)
// ---------------------------------------------------------------------------
__global__ __launch_bounds__(256) void convert_kernel(const float* __restrict__ x,
                                                      const float* __restrict__ Wq,
                                                      const float* __restrict__ Wk,
                                                      const float* __restrict__ Wv) {
    const int id = blockIdx.x;
    const float* src;
    __half* d;
    size_t i;
    if (id < 8192) {
        src = x; d = g_xf;
        i = (size_t)id * 256 + threadIdx.x;
    } else {
        int t = id - 8192;
        int z = t >> 8;
        src = (z == 0) ? Wq : (z == 1) ? Wk : Wv;
        d = g_wf + (size_t)z * D_ * D_;
        i = (size_t)(t & 255) * 256 + threadIdx.x;
    }
    float4 v = ((const float4*)src)[i];
    ((__half2*)d)[i * 2]     = __floats2half2_rn(v.x, v.y);
    ((__half2*)d)[i * 2 + 1] = __floats2half2_rn(v.z, v.w);
}

// ---------------------------------------------------------------------------
// QKV projection GEMM (z: 0=q, 1=k, 2=v transposed). fp16 single product.
// Dead m-tiles skipped for q,k.
// ---------------------------------------------------------------------------
__global__ __launch_bounds__(256, 2) void qkv_mma_kernel(const float* __restrict__ bq,
                                                         const float* __restrict__ bk,
                                                         const float* __restrict__ bv,
                                                         const void* __restrict__ lens) {
    extern __shared__ char dyn[];
    uint32_t sb = smem_u32(dyn);
    const int tid = threadIdx.x, lane = tid & 31, wid = tid >> 5;
    const int wm = wid & 3, wn = wid >> 2;
    const int z = blockIdx.z;
    const int m0 = blockIdx.y * 128, n0 = blockIdx.x * 128;

    if (z < 2) {
        const long long L = get_len(lens, m0 >> 11);
        if ((m0 & 2047) >= L) return;
    }

    float acc[2][8][4] = {};
    gemm_mainloop1(g_xf, D_, g_wf + (size_t)z * D_ * D_, D_,
                   m0, n0, D_ / 64, sb, tid, acc);

    const float* bias = (z == 0) ? bq : (z == 1) ? bk : bv;

    if (z < 2) {
        __half* o = (z == 0) ? g_qf : g_kf;
        #pragma unroll
        for (int ma = 0; ma < 2; ma++) {
            int m = m0 + wm * 32 + ma * 16 + (lane >> 2);
            #pragma unroll
            for (int na = 0; na < 8; na++) {
                int n = n0 + wn * 64 + na * 8 + (lane & 3) * 2;
                float bv0 = __ldg(bias + n), bv1 = __ldg(bias + n + 1);
                *(__half2*)(o + (size_t)m * D_ + n) =
                    __floats2half2_rn(acc[ma][na][0] + bv0, acc[ma][na][1] + bv1);
                *(__half2*)(o + (size_t)(m + 8) * D_ + n) =
                    __floats2half2_rn(acc[ma][na][2] + bv0, acc[ma][na][3] + bv1);
            }
        }
    } else {
        // V: stage fp32 tile in SMEM, write transposed fp16 [b][d][n]
        __syncthreads();
        float* sf = (float*)dyn;   // [128][129] fp32 = 66KB
        #pragma unroll
        for (int ma = 0; ma < 2; ma++) {
            int r = wm * 32 + ma * 16 + (lane >> 2);
            #pragma unroll
            for (int na = 0; na < 8; na++) {
                int nl = wn * 64 + na * 8 + (lane & 3) * 2;
                float bv0 = __ldg(bias + n0 + nl), bv1 = __ldg(bias + n0 + nl + 1);
                sf[r * 129 + nl]           = acc[ma][na][0] + bv0;
                sf[r * 129 + nl + 1]       = acc[ma][na][1] + bv1;
                sf[(r + 8) * 129 + nl]     = acc[ma][na][2] + bv0;
                sf[(r + 8) * 129 + nl + 1] = acc[ma][na][3] + bv1;
            }
        }
        __syncthreads();
        const int b = m0 >> 11;
        const int mloc = m0 & 2047;
        int d = tid >> 1;                  // 0..127 (local head dim)
        int ms = (tid & 1) * 64;           // m segment
        __half* o = g_vtf + ((size_t)b * D_ + n0 + d) * N_ + mloc + ms;
        #pragma unroll
        for (int c = 0; c < 64; c += 2)
            *(__half2*)(o + c) = __floats2half2_rn(sf[(ms + c) * 129 + d],
                                                   sf[(ms + c + 1) * 129 + d]);
    }
}

// ---------------------------------------------------------------------------
// SCORES+COLMEAN: ids 0..2047 = scores tiles (128q x 128k, fused exp, fp16
// numerators, psum partials); ids 2048..2559 = colmean(V) rows.
// colmean depends only on Vt (ready) and backfills dead scores-tile slots.
// ---------------------------------------------------------------------------
__global__ __launch_bounds__(256, 2) void scores_mma_kernel(const void* __restrict__ lens) {
    const int id = blockIdx.x;
    const int tid = threadIdx.x, lane = tid & 31, wid = tid >> 5;

    if (id >= 2048) {
        // ---- colmean: 8 rows of Vt per CTA, one per warp ----
        int gw = (id - 2048) * 8 + wid;    // 0 .. B_*D_-1
        const __half2* ph = (const __half2*)(g_vtf + (size_t)gw * N_);
        float s = 0.f;
        for (int i = lane; i < N_ / 2; i += 32) {
            float2 f = __half22float2(ph[i]);
            s += f.x + f.y;
        }
        #pragma unroll
        for (int o = 16; o > 0; o >>= 1) s += __shfl_xor_sync(0xffffffffu, s, o);
        if (lane == 0) g_mean[gw] = s * (1.0f / N_);
        return;
    }

    const int b = id >> 8;
    const int m0 = ((id >> 4) & 15) * 128, n0 = (id & 15) * 128;
    const long long L = get_len(lens, b);
    if (m0 >= L || n0 >= L) return;

    extern __shared__ char dyn[];
    uint32_t sb = smem_u32(dyn);
    const int wm = wid & 3, wn = wid >> 2;

    float acc[2][8][4] = {};
    const size_t off = (size_t)b * N_ * D_;
    gemm_mainloop1(g_qf + off, D_, g_kf + off, D_, m0, n0, D_ / 64, sb, tid, acc);

    float rsum[2][2] = {};
    #pragma unroll
    for (int ma = 0; ma < 2; ma++) {
        int q0 = m0 + wm * 32 + ma * 16 + (lane >> 2);
        #pragma unroll
        for (int na = 0; na < 8; na++) {
            int kj = n0 + wn * 64 + na * 8 + (lane & 3) * 2;
            bool k0d = (kj >= L), k1d = (kj + 1 >= L);
            #pragma unroll
            for (int h = 0; h < 2; h++) {
                int q = q0 + h * 8;
                bool qd = (q >= L);
                float e0 = (qd || k0d) ? 0.f : __expf(acc[ma][na][h * 2]     * SCALE);
                float e1 = (qd || k1d) ? 0.f : __expf(acc[ma][na][h * 2 + 1] * SCALE);
                __half2 hp = __floats2half2_rn(e0, e1);
                *(__half2*)(g_pf + ((size_t)b * N_ + q) * N_ + kj) = hp;
                float2 fr = __half22float2(hp);   // rounded, for consistent norm
                rsum[ma][h] += fr.x + fr.y;
            }
        }
    }
    __syncthreads();
    float* ps = (float*)dyn;   // [128][2]
    #pragma unroll
    for (int ma = 0; ma < 2; ma++)
        #pragma unroll
        for (int h = 0; h < 2; h++) {
            float v = rsum[ma][h];
            v += __shfl_xor_sync(0xffffffffu, v, 1);
            v += __shfl_xor_sync(0xffffffffu, v, 2);
            if ((lane & 3) == 0) {
                int r = wm * 32 + ma * 16 + (lane >> 2) + h * 8;
                ps[r * 2 + wn] = v;
            }
        }
    __syncthreads();
    if (tid < 128) {
        float t = ps[tid * 2] + ps[tid * 2 + 1];
        g_psum[((size_t)b * 16 + (n0 >> 7)) * N_ + m0 + tid] = t;
    }
}

// ---------------------------------------------------------------------------
// OUT+FILL: ids 0..511 = PV GEMM (128q x 128d tiles, rinv computed in-CTA
// from psum partials, stores pred m<L); ids 512..8703 = fill dead rows.
// ---------------------------------------------------------------------------
__global__ __launch_bounds__(256, 2) void out_fill_kernel(float* __restrict__ Out,
                                                          const void* __restrict__ lens) {
    const int id = blockIdx.x;
    if (id >= 512) {
        int t = id - 512;                  // 0..8191
        int b = t >> 10;
        const long long L = get_len(lens, b);
        int qi = ((t & 1023) << 1) + (threadIdx.x >> 7);
        if (qi < L) return;
        int c = threadIdx.x & 127;
        float4 v = ((const float4*)(g_mean + (size_t)b * D_))[c];
        ((float4*)(Out + ((size_t)b * N_ + qi) * D_))[c] = v;
        return;
    }

    const int b = id >> 6;
    const int rem = id & 63;
    const int m0 = (rem >> 2) * 128, n0 = (rem & 3) * 128;
    const long long L = get_len(lens, b);
    if (m0 >= L) return;
    const int Lpad = ((int)L + 127) & ~127;

    extern __shared__ char dyn[];
    uint32_t sb = smem_u32(dyn);
    const int tid = threadIdx.x, lane = tid & 31, wid = tid >> 5;
    const int wm = wid & 3, wn = wid >> 2;

    float acc[2][8][4] = {};
    gemm_mainloop1(g_pf + (size_t)b * N_ * N_, N_,
                   g_vtf + (size_t)b * D_ * N_, N_,
                   m0, n0, Lpad / 64, sb, tid, acc);

    // In-CTA rinv: sum 16 psum partials per row (same order as old rinv kernel)
    __syncthreads();
    float* pr = (float*)dyn;   // [128]
    if (tid < 128) {
        float s = 0.f;
        #pragma unroll
        for (int t = 0; t < 16; t++)
            s += g_psum[((size_t)b * 16 + t) * N_ + m0 + tid];
        pr[tid] = (s > 0.f) ? 1.0f / s : 0.f;
    }
    __syncthreads();

    #pragma unroll
    for (int ma = 0; ma < 2; ma++) {
        int r = wm * 32 + ma * 16 + (lane >> 2);
        int m = m0 + r;
        float ri0 = pr[r];
        float ri1 = pr[r + 8];
        float* r0 = Out + ((size_t)b * N_ + m) * D_;
        float* r1 = Out + ((size_t)b * N_ + m + 8) * D_;
        #pragma unroll
        for (int na = 0; na < 8; na++) {
            int n = n0 + wn * 64 + na * 8 + (lane & 3) * 2;
            if (m < L)
                *(float2*)(r0 + n) = make_float2(acc[ma][na][0] * ri0, acc[ma][na][1] * ri0);
            if (m + 8 < L)
                *(float2*)(r1 + n) = make_float2(acc[ma][na][2] * ri1, acc[ma][na][3] * ri1);
        }
    }
}

// ---------------------------------------------------------------------------
extern "C" void kernel_launch(void* const* d_in, const int* in_sizes, int n_in,
                              void* d_out, int out_size)
{
    const float* x    = (const float*)d_in[0];
    const void*  lens = d_in[1];
    const float* Wq   = (const float*)d_in[2];
    const float* bq   = (const float*)d_in[3];
    const float* Wk   = (const float*)d_in[4];
    const float* bk   = (const float*)d_in[5];
    const float* Wv   = (const float*)d_in[6];
    const float* bv   = (const float*)d_in[7];
    float* out = (float*)d_out;

    cudaFuncSetAttribute(qkv_mma_kernel,    cudaFuncAttributeMaxDynamicSharedMemorySize, SMEM_BYTES);
    cudaFuncSetAttribute(scores_mma_kernel, cudaFuncAttributeMaxDynamicSharedMemorySize, SMEM_BYTES);
    cudaFuncSetAttribute(out_fill_kernel,   cudaFuncAttributeMaxDynamicSharedMemorySize, SMEM_BYTES);

    convert_kernel<<<8960, 256>>>(x, Wq, Wk, Wv);
    qkv_mma_kernel<<<dim3(D_ / 128, M_ / 128, 3), 256, SMEM_BYTES>>>(bq, bk, bv, lens);
    scores_mma_kernel<<<2048 + 512, 256, SMEM_BYTES>>>(lens);
    out_fill_kernel<<<512 + 8192, 256, SMEM_BYTES>>>(out, lens);
}